// round 1
// baseline (speedup 1.0000x reference)
#include <cuda_runtime.h>
#include <math_constants.h>

#define L   8192
#define D   64
#define BM  64
#define BN  64
#define NT  256

// Scratch for per-row softmax stats (allocation-free rule: __device__ globals)
__device__ float g_m[L];
__device__ float g_l[L];

// ---------------------------------------------------------------------------
// Pass 1: raw scores S = Q K^T written to the score region of d_out,
// plus online per-row max (g_m) and sum-of-exp (g_l).
// Each CTA owns BM=64 query rows; iterates over all 8192 keys in BN=64 tiles.
// ---------------------------------------------------------------------------
__global__ __launch_bounds__(NT) void pass1_kernel(const float* __restrict__ Q,
                                                   const float* __restrict__ Km,
                                                   float* __restrict__ S) {
    __shared__ float sQt[D][BM + 4];   // transposed, padded: float4-aligned rows
    __shared__ float sKt[D][BN + 4];
    __shared__ float red[BM][16];
    __shared__ float m_s[BM], l_s[BM], mold[BM];

    const int tid = threadIdx.x;
    const int tx  = tid & 15;
    const int ty  = tid >> 4;
    const int r0  = ty * 4;
    const int c0  = tx * 4;
    const int rowblk = blockIdx.x * BM;

    // Load Q block transposed into smem (once per CTA)
    for (int idx = tid; idx < BM * D; idx += NT) {
        const int r = idx >> 6;
        const int d = idx & 63;
        sQt[d][r] = Q[(rowblk + r) * D + d];
    }
    if (tid < BM) { m_s[tid] = -CUDART_INF_F; l_s[tid] = 0.0f; }
    __syncthreads();

    for (int kb = 0; kb < L; kb += BN) {
        // Load K tile transposed
        for (int idx = tid; idx < BN * D; idx += NT) {
            const int c = idx >> 6;
            const int d = idx & 63;
            sKt[d][c] = Km[(kb + c) * D + d];
        }
        __syncthreads();

        // 4x4 register microtile GEMM over d
        float acc[4][4];
#pragma unroll
        for (int i = 0; i < 4; i++)
#pragma unroll
            for (int j = 0; j < 4; j++) acc[i][j] = 0.0f;

#pragma unroll 8
        for (int d = 0; d < D; d++) {
            const float4 qf = *reinterpret_cast<const float4*>(&sQt[d][r0]);
            const float4 kf = *reinterpret_cast<const float4*>(&sKt[d][c0]);
            const float qa[4] = {qf.x, qf.y, qf.z, qf.w};
            const float ka[4] = {kf.x, kf.y, kf.z, kf.w};
#pragma unroll
            for (int i = 0; i < 4; i++)
#pragma unroll
                for (int j = 0; j < 4; j++)
                    acc[i][j] = fmaf(qa[i], ka[j], acc[i][j]);
        }

        // Write raw logits (scratch; overwritten by pass 2 with softmax)
#pragma unroll
        for (int i = 0; i < 4; i++) {
            float4 w = make_float4(acc[i][0], acc[i][1], acc[i][2], acc[i][3]);
            *reinterpret_cast<float4*>(
                &S[(size_t)(rowblk + r0 + i) * L + kb + c0]) = w;
        }

        // --- online stats: row max ---
#pragma unroll
        for (int i = 0; i < 4; i++) {
            float mx = fmaxf(fmaxf(acc[i][0], acc[i][1]),
                             fmaxf(acc[i][2], acc[i][3]));
            red[r0 + i][tx] = mx;
        }
        __syncthreads();
        if (tid < BM) {
            float mx = m_s[tid];
            mold[tid] = mx;
#pragma unroll
            for (int t = 0; t < 16; t++) mx = fmaxf(mx, red[tid][t]);
            m_s[tid] = mx;
        }
        __syncthreads();

        // --- online stats: sum of exp under the new max ---
#pragma unroll
        for (int i = 0; i < 4; i++) {
            const float mi = m_s[r0 + i];
            float se = __expf(acc[i][0] - mi) + __expf(acc[i][1] - mi) +
                       __expf(acc[i][2] - mi) + __expf(acc[i][3] - mi);
            red[r0 + i][tx] = se;
        }
        __syncthreads();
        if (tid < BM) {
            float s = 0.0f;
#pragma unroll
            for (int t = 0; t < 16; t++) s += red[tid][t];
            l_s[tid] = l_s[tid] * __expf(mold[tid] - m_s[tid]) + s;
        }
        __syncthreads();   // also guards sKt reuse next iteration
    }

    if (tid < BM) {
        g_m[rowblk + tid] = m_s[tid];
        g_l[rowblk + tid] = l_s[tid];
    }
}

// ---------------------------------------------------------------------------
// Pass 2: read raw logits, write normalized softmax in place,
// accumulate O = P V with register tiling.
// ---------------------------------------------------------------------------
__global__ __launch_bounds__(NT) void pass2_kernel(const float* __restrict__ V,
                                                   float* __restrict__ S,
                                                   float* __restrict__ O) {
    __shared__ float sP[BM][BN];
    __shared__ float sV[BN][D];
    __shared__ float m_s[BM], li_s[BM];

    const int tid = threadIdx.x;
    const int tx  = tid & 15;
    const int ty  = tid >> 4;
    const int r0  = ty * 4;
    const int c0  = tx * 4;     // score columns handled by this thread
    const int d0  = tx * 4;     // out columns handled by this thread
    const int rowblk = blockIdx.x * BM;

    if (tid < BM) {
        m_s[tid]  = g_m[rowblk + tid];
        li_s[tid] = 1.0f / g_l[rowblk + tid];
    }

    float acc[4][4];
#pragma unroll
    for (int i = 0; i < 4; i++)
#pragma unroll
        for (int j = 0; j < 4; j++) acc[i][j] = 0.0f;

    __syncthreads();

    for (int kb = 0; kb < L; kb += BN) {
        // V tile is contiguous in gmem: straight float4 copy
        {
            const float4* vsrc = reinterpret_cast<const float4*>(V + (size_t)kb * D);
            float4*       vdst = reinterpret_cast<float4*>(&sV[0][0]);
            for (int idx = tid; idx < BN * D / 4; idx += NT) vdst[idx] = vsrc[idx];
        }

        // Read raw logits, normalize, write softmax back + stage in smem
#pragma unroll
        for (int i = 0; i < 4; i++) {
            float* srow = &S[(size_t)(rowblk + r0 + i) * L + kb + c0];
            float4 s4 = *reinterpret_cast<const float4*>(srow);
            const float mi = m_s[r0 + i];
            const float sc = li_s[r0 + i];
            float4 p4;
            p4.x = __expf(s4.x - mi) * sc;
            p4.y = __expf(s4.y - mi) * sc;
            p4.z = __expf(s4.z - mi) * sc;
            p4.w = __expf(s4.w - mi) * sc;
            *reinterpret_cast<float4*>(srow) = p4;
            *reinterpret_cast<float4*>(&sP[r0 + i][c0]) = p4;
        }
        __syncthreads();

        // O += P_tile * V_tile
#pragma unroll 4
        for (int c = 0; c < BN; c++) {
            const float4 vf = *reinterpret_cast<const float4*>(&sV[c][d0]);
            const float va[4] = {vf.x, vf.y, vf.z, vf.w};
            float pa[4];
#pragma unroll
            for (int i = 0; i < 4; i++) pa[i] = sP[r0 + i][c];
#pragma unroll
            for (int i = 0; i < 4; i++)
#pragma unroll
                for (int j = 0; j < 4; j++)
                    acc[i][j] = fmaf(pa[i], va[j], acc[i][j]);
        }
        __syncthreads();
    }

#pragma unroll
    for (int i = 0; i < 4; i++) {
        float4 w = make_float4(acc[i][0], acc[i][1], acc[i][2], acc[i][3]);
        *reinterpret_cast<float4*>(&O[(size_t)(rowblk + r0 + i) * D + d0]) = w;
    }
}

extern "C" void kernel_launch(void* const* d_in, const int* in_sizes, int n_in,
                              void* d_out, int out_size) {
    const float* q = (const float*)d_in[0];
    const float* k = (const float*)d_in[1];
    const float* v = (const float*)d_in[2];

    float* out   = (float*)d_out;          // [L, D]
    float* score = out + (size_t)L * D;    // [L, L]

    pass1_kernel<<<L / BM, NT>>>(q, k, score);
    pass2_kernel<<<L / BM, NT>>>(v, score, out);
}

// round 2
// speedup vs baseline: 2.6260x; 2.6260x over previous
#include <cuda_runtime.h>
#include <math_constants.h>

#define L     8192
#define D     64
#define BM    64
#define NCH   8
#define CHUNK 1024          // L / NCH
#define BN1   128           // pass1 key-tile width
#define T1    (CHUNK/BN1)   // 8 tiles per chunk (pass1)
#define BN2   64            // pass2 key-tile width
#define T2    (CHUNK/BN2)   // 16 tiles per chunk (pass2)
#define NT    256

// Scratch (allocation-free rule: __device__ globals)
__device__ float g_mp[NCH * L];            // per-chunk partial row max
__device__ float g_lp[NCH * L];            // per-chunk partial sum-of-exp
__device__ float g_m[L];                   // final row max
__device__ float g_li[L];                  // final 1/l
__device__ float g_opart[(size_t)NCH * L * D];  // per-chunk partial O (16 MB)

// ---------------------------------------------------------------------------
// Pass 1: raw S = Q K^T for a 64-row x 1024-col strip + per-chunk m/l stats.
// Thread layout: 8 warps, warp w owns rows r0 = w*8 .. w*8+7 (q reads are
// broadcasts, stats reduce fully inside the warp). Lane tx owns 4 columns.
// ---------------------------------------------------------------------------
__global__ __launch_bounds__(NT) void pass1_kernel(const float* __restrict__ Q,
                                                   const float* __restrict__ Km,
                                                   float* __restrict__ S) {
    __shared__ float sQt[D][BM + 4];   // transposed, +4 pad keeps float4 align
    __shared__ float sKt[D][BN1 + 4];

    const int tid = threadIdx.x;
    const int tx  = tid & 31;
    const int wid = tid >> 5;
    const int r0  = wid * 8;
    const int c0  = tx * 4;
    const int rowblk  = blockIdx.y * BM;
    const int colbase = blockIdx.x * CHUNK;

    for (int idx = tid; idx < BM * D; idx += NT) {
        const int r = idx >> 6;
        const int d = idx & 63;
        sQt[d][r] = Q[(rowblk + r) * D + d];
    }

    float m[8], l[8];
#pragma unroll
    for (int i = 0; i < 8; i++) { m[i] = -CUDART_INF_F; l[i] = 0.0f; }
    __syncthreads();

    for (int t = 0; t < T1; t++) {
        const int kb = colbase + t * BN1;
        for (int idx = tid; idx < BN1 * D; idx += NT) {
            const int c = idx >> 6;
            const int d = idx & 63;
            sKt[d][c] = Km[(size_t)(kb + c) * D + d];
        }
        __syncthreads();

        float acc[8][4];
#pragma unroll
        for (int i = 0; i < 8; i++)
#pragma unroll
            for (int j = 0; j < 4; j++) acc[i][j] = 0.0f;

#pragma unroll 8
        for (int d = 0; d < D; d++) {
            const float4 q0 = *reinterpret_cast<const float4*>(&sQt[d][r0]);
            const float4 q1 = *reinterpret_cast<const float4*>(&sQt[d][r0 + 4]);
            const float4 kf = *reinterpret_cast<const float4*>(&sKt[d][c0]);
            const float qa[8] = {q0.x, q0.y, q0.z, q0.w, q1.x, q1.y, q1.z, q1.w};
            const float ka[4] = {kf.x, kf.y, kf.z, kf.w};
#pragma unroll
            for (int i = 0; i < 8; i++)
#pragma unroll
                for (int j = 0; j < 4; j++)
                    acc[i][j] = fmaf(qa[i], ka[j], acc[i][j]);
        }

        // Raw logits out (pass2 overwrites with normalized softmax)
#pragma unroll
        for (int i = 0; i < 8; i++) {
            *reinterpret_cast<float4*>(
                &S[(size_t)(rowblk + r0 + i) * L + kb + c0]) =
                make_float4(acc[i][0], acc[i][1], acc[i][2], acc[i][3]);
        }

        // Per-thread online stats over this thread's 4 columns
#pragma unroll
        for (int i = 0; i < 8; i++) {
            const float mx = fmaxf(fmaxf(acc[i][0], acc[i][1]),
                                   fmaxf(acc[i][2], acc[i][3]));
            const float nm = fmaxf(m[i], mx);
            l[i] = l[i] * __expf(m[i] - nm) +
                   __expf(acc[i][0] - nm) + __expf(acc[i][1] - nm) +
                   __expf(acc[i][2] - nm) + __expf(acc[i][3] - nm);
            m[i] = nm;
        }
        __syncthreads();
    }

    // Warp-level combine of the 32 per-lane (m,l) pairs for each owned row
#pragma unroll
    for (int i = 0; i < 8; i++) {
        float mi = m[i], li = l[i];
#pragma unroll
        for (int off = 16; off; off >>= 1) {
            const float om = __shfl_xor_sync(0xffffffffu, mi, off);
            const float ol = __shfl_xor_sync(0xffffffffu, li, off);
            const float nm = fmaxf(mi, om);
            li = li * __expf(mi - nm) + ol * __expf(om - nm);
            mi = nm;
        }
        if (tx == 0) {
            g_mp[blockIdx.x * L + rowblk + r0 + i] = mi;
            g_lp[blockIdx.x * L + rowblk + r0 + i] = li;
        }
    }
}

// ---------------------------------------------------------------------------
// Combine per-chunk stats into final per-row (m, 1/l)
// ---------------------------------------------------------------------------
__global__ void combine_kernel() {
    const int row = blockIdx.x * 256 + threadIdx.x;
    float m = -CUDART_INF_F;
#pragma unroll
    for (int c = 0; c < NCH; c++) m = fmaxf(m, g_mp[c * L + row]);
    float l = 0.0f;
#pragma unroll
    for (int c = 0; c < NCH; c++)
        l += g_lp[c * L + row] * __expf(g_mp[c * L + row] - m);
    g_m[row]  = m;
    g_li[row] = 1.0f / l;
}

// ---------------------------------------------------------------------------
// Pass 2: normalize raw logits in place + partial O for this chunk
// ---------------------------------------------------------------------------
__global__ __launch_bounds__(NT) void pass2_kernel(const float* __restrict__ V,
                                                   float* __restrict__ S) {
    __shared__ float sP[BM][BN2];
    __shared__ float sV[BN2][D];
    __shared__ float m_s[BM], li_s[BM];

    const int tid = threadIdx.x;
    const int tx  = tid & 15;
    const int ty  = tid >> 4;
    const int r0  = ty * 4;
    const int c0  = tx * 4;
    const int d0  = tx * 4;
    const int rowblk  = blockIdx.y * BM;
    const int colbase = blockIdx.x * CHUNK;

    if (tid < BM) {
        m_s[tid]  = g_m[rowblk + tid];
        li_s[tid] = g_li[rowblk + tid];
    }

    float acc[4][4];
#pragma unroll
    for (int i = 0; i < 4; i++)
#pragma unroll
        for (int j = 0; j < 4; j++) acc[i][j] = 0.0f;

    __syncthreads();

    for (int t = 0; t < T2; t++) {
        const int kb = colbase + t * BN2;
        {
            const float4* vsrc = reinterpret_cast<const float4*>(V + (size_t)kb * D);
            float4*       vdst = reinterpret_cast<float4*>(&sV[0][0]);
            for (int idx = tid; idx < BN2 * D / 4; idx += NT) vdst[idx] = vsrc[idx];
        }

#pragma unroll
        for (int i = 0; i < 4; i++) {
            float* srow = &S[(size_t)(rowblk + r0 + i) * L + kb + c0];
            float4 s4 = *reinterpret_cast<const float4*>(srow);
            const float mi = m_s[r0 + i];
            const float sc = li_s[r0 + i];
            float4 p4;
            p4.x = __expf(s4.x - mi) * sc;
            p4.y = __expf(s4.y - mi) * sc;
            p4.z = __expf(s4.z - mi) * sc;
            p4.w = __expf(s4.w - mi) * sc;
            *reinterpret_cast<float4*>(srow) = p4;
            *reinterpret_cast<float4*>(&sP[r0 + i][c0]) = p4;
        }
        __syncthreads();

#pragma unroll 4
        for (int c = 0; c < BN2; c++) {
            const float4 vf = *reinterpret_cast<const float4*>(&sV[c][d0]);
            const float va[4] = {vf.x, vf.y, vf.z, vf.w};
            float pa[4];
#pragma unroll
            for (int i = 0; i < 4; i++) pa[i] = sP[r0 + i][c];
#pragma unroll
            for (int i = 0; i < 4; i++)
#pragma unroll
                for (int j = 0; j < 4; j++)
                    acc[i][j] = fmaf(pa[i], va[j], acc[i][j]);
        }
        __syncthreads();
    }

    float* op = g_opart + ((size_t)blockIdx.x * L + rowblk) * D;
#pragma unroll
    for (int i = 0; i < 4; i++) {
        *reinterpret_cast<float4*>(&op[(r0 + i) * D + d0]) =
            make_float4(acc[i][0], acc[i][1], acc[i][2], acc[i][3]);
    }
}

// ---------------------------------------------------------------------------
// Reduce the NCH partial O buffers into the final O
// ---------------------------------------------------------------------------
__global__ void reduce_o_kernel(float* __restrict__ O) {
    const size_t idx = (size_t)blockIdx.x * 256 + threadIdx.x;   // float4 index
    float4 s = make_float4(0.f, 0.f, 0.f, 0.f);
#pragma unroll
    for (int c = 0; c < NCH; c++) {
        const float4 v = *reinterpret_cast<const float4*>(
            &g_opart[(size_t)c * L * D + idx * 4]);
        s.x += v.x; s.y += v.y; s.z += v.z; s.w += v.w;
    }
    *reinterpret_cast<float4*>(&O[idx * 4]) = s;
}

extern "C" void kernel_launch(void* const* d_in, const int* in_sizes, int n_in,
                              void* d_out, int out_size) {
    const float* q = (const float*)d_in[0];
    const float* k = (const float*)d_in[1];
    const float* v = (const float*)d_in[2];

    float* out   = (float*)d_out;          // [L, D]
    float* score = out + (size_t)L * D;    // [L, L]

    dim3 grid(NCH, L / BM);
    pass1_kernel<<<grid, NT>>>(q, k, score);
    combine_kernel<<<L / 256, 256>>>();
    pass2_kernel<<<grid, NT>>>(v, score);
    reduce_o_kernel<<<(L * D / 4) / 256, 256>>>(out);
}